// round 4
// baseline (speedup 1.0000x reference)
#include <cuda_runtime.h>

#define NBINS 4096            // 16^3
#define NPAIR (NBINS / 2)
#define BLOCKS 296
#define THREADS 768
#define NWARPS (THREADS / 32)

// Zero-initialized at load; kernel self-cleans both for graph-replay determinism.
__device__ unsigned long long g_hist64[NPAIR];
__device__ unsigned int g_arrival;

__device__ __forceinline__ int qbin(float c) {
    int q = (int)(c * 15.0f);          // trunc == astype(int32); inputs are >= 0
    return q > 15 ? 15 : q;            // NaN/1.0 safety; no lower clamp needed
}

__device__ __forceinline__ int flat3(float r, float g, float b) {
    return (qbin(r) << 8) + (qbin(g) << 4) + qbin(b);
}

// Pack 4 quantized nibbles of a float4 into 16 bits.
__device__ __forceinline__ unsigned int pack4(float4 v) {
    return (unsigned)qbin(v.x) | ((unsigned)qbin(v.y) << 4) |
           ((unsigned)qbin(v.z) << 8) | ((unsigned)qbin(v.w) << 12);
}

__global__ void __launch_bounds__(THREADS, 2) fused_hist_loss_kernel(
        const float4* __restrict__ srcv, const float* __restrict__ src,
        const float* __restrict__ pal,
        int ntiles, int npix, int M, float* __restrict__ out) {
    __shared__ unsigned int sh[NBINS];
    __shared__ float red[NWARPS];
    __shared__ bool is_last;

    for (int i = threadIdx.x; i < NBINS; i += THREADS) sh[i] = 0u;
    __syncthreads();

    const int lane = threadIdx.x & 31;
    const int gwarp = (blockIdx.x * THREADS + threadIdx.x) >> 5;
    const int nwarps_total = (BLOCKS * THREADS) >> 5;

    // Per-lane gather constants (depend on lane only): pixel j = 32*g + lane
    // needs nibbles n=3j..3j+2; nibble n lives in lane (n>>2)&31 at bit
    // 16*(n>>7) + 4*(n&3) of that lane's packed u64.
    int l0[4], l2[4], sh0[4], sh1[4], sh2[4];
    bool midlo[4];
    #pragma unroll
    for (int g = 0; g < 4; g++) {
        int j = 32 * g + lane;
        int n0 = 3 * j;
        l0[g] = (n0 >> 2) & 31;
        int l1 = ((n0 + 1) >> 2) & 31;
        l2[g] = ((n0 + 2) >> 2) & 31;
        sh0[g] = ((n0 >> 7) << 4) + ((n0 & 3) << 2);
        sh1[g] = (((n0 + 1) >> 7) << 4) + (((n0 + 1) & 3) << 2);
        sh2[g] = (((n0 + 2) >> 7) << 4) + (((n0 + 2) & 3) << 2);
        midlo[g] = (l1 == l0[g]);
    }

    // Each warp-tile = 128 pixels = 96 float4 = 1536 B contiguous.
    // All three LDG.128 are warp-contiguous (512 B each -> 4 wavefronts,
    // vs 12 for the old stride-48B layout). Misalignment between float4
    // boundaries and pixel triples is resolved with register shuffles of
    // packed 4-bit bins (shuffle unit, not the l1tex crossbar).
    for (int t = gwarp; t < ntiles; t += nwarps_total) {
        const float4* base = srcv + (size_t)t * 96;
        float4 A = __ldcs(base + lane);
        float4 B = __ldcs(base + 32 + lane);
        float4 C = __ldcs(base + 64 + lane);
        unsigned long long P =
            (unsigned long long)pack4(A) |
            ((unsigned long long)pack4(B) << 16) |
            ((unsigned long long)pack4(C) << 32);

        #pragma unroll
        for (int g = 0; g < 4; g++) {
            unsigned long long S0 = __shfl_sync(0xffffffffu, P, l0[g]);
            unsigned long long S2 = __shfl_sync(0xffffffffu, P, l2[g]);
            unsigned q0 = (unsigned)(S0 >> sh0[g]) & 15u;
            unsigned long long Sm = midlo[g] ? S0 : S2;
            unsigned q1 = (unsigned)(Sm >> sh1[g]) & 15u;
            unsigned q2 = (unsigned)(S2 >> sh2[g]) & 15u;
            atomicAdd(&sh[(q0 << 8) | (q1 << 4) | q2], 1u);
        }
    }
    // tail pixels (npix % 128 == 0 here; kept for generality)
    for (int p = ntiles * 128 + (gwarp * 32 + lane); p < npix;
         p += nwarps_total * 32) {
        atomicAdd(&sh[flat3(src[3 * p], src[3 * p + 1], src[3 * p + 2])], 1u);
    }
    __syncthreads();

    // Flush: pack two u32 bin counts into one u64 atomic.
    for (int i = threadIdx.x; i < NPAIR; i += THREADS) {
        unsigned int lo = sh[2 * i], hi = sh[2 * i + 1];
        if (lo | hi)
            atomicAdd(&g_hist64[i],
                      (unsigned long long)lo | ((unsigned long long)hi << 32));
    }
    __threadfence();
    if (threadIdx.x == 0) {
        unsigned int tkt = atomicAdd(&g_arrival, 1u);
        is_last = (tkt == BLOCKS - 1);
    }
    __syncthreads();
    if (!is_last) return;

    // ---- last block: palette histogram + L1 loss + self-clean ----
    for (int i = threadIdx.x; i < NBINS; i += THREADS) sh[i] = 0u;
    __syncthreads();
    for (int p = threadIdx.x; p < M; p += THREADS) {
        atomicAdd(&sh[flat3(pal[3 * p], pal[3 * p + 1], pal[3 * p + 2])], 1u);
    }
    __syncthreads();

    const float invS = 1.0f / ((float)npix + 1e-8f);
    const float invT = 1.0f / ((float)M + 1e-8f);

    float acc = 0.0f;
    for (int i = threadIdx.x; i < NPAIR; i += THREADS) {
        unsigned long long v = __ldcg(&g_hist64[i]);
        unsigned int lo = (unsigned int)v;
        unsigned int hi = (unsigned int)(v >> 32);
        acc += fabsf((float)lo * invS - (float)sh[2 * i]     * invT);
        acc += fabsf((float)hi * invS - (float)sh[2 * i + 1] * invT);
        g_hist64[i] = 0ull;                      // self-clean for next replay
    }

    for (int off = 16; off; off >>= 1) acc += __shfl_down_sync(0xffffffffu, acc, off);
    if ((threadIdx.x & 31) == 0) red[threadIdx.x >> 5] = acc;
    __syncthreads();
    if (threadIdx.x < 32) {
        float v = (threadIdx.x < NWARPS) ? red[threadIdx.x] : 0.0f;
        for (int off = 16; off; off >>= 1) v += __shfl_down_sync(0xffffffffu, v, off);
        if (threadIdx.x == 0) {
            out[0] = v * (1.0f / (float)NBINS);
            g_arrival = 0u;                      // self-clean for next replay
        }
    }
}

extern "C" void kernel_launch(void* const* d_in, const int* in_sizes, int n_in,
                              void* d_out, int out_size) {
    const float* src = (const float*)d_in[0];   // (N, 3) float32
    const float* pal = (const float*)d_in[1];   // (M, 3) float32
    int N = in_sizes[0] / 3;
    int M = in_sizes[1] / 3;
    int ntiles = N / 128;

    fused_hist_loss_kernel<<<BLOCKS, THREADS>>>(
        (const float4*)src, src, pal, ntiles, N, M, (float*)d_out);
}